// round 4
// baseline (speedup 1.0000x reference)
#include <cuda_runtime.h>
#include <cuda_fp16.h>
#include <math.h>

#define Bc 16
#define Nc 127
#define Sc 32
#define Ec 16
#define Vc 128
#define BTc 2048

__device__ float g_xbuf[BTc * Ec];     // u + o per bt

// smem layout (floats)
#define OFF_HIST  0                     // [128][33] per-s private histograms
#define OFF_G     (128*33)              // __half2[128] packed (g0,g1)
#define OFF_SIDX  (OFF_G + 128)         // uint32 [128][8]
#define OFF_UPART (OFF_SIDX + 1024)     // [32][33]
#define OFF_U     (OFF_UPART + 1056)    // [16]
#define OFF_AU    (OFF_U + 16)          // [16]
#define OFF_A     (OFF_AU + 16)         // [16]
#define OFF_B     (OFF_A + 16)          // [32]
#define OFF_PROBS (OFF_B + 32)          // [128]
#define OFF_RED   (OFF_PROBS + 128)     // [32]
#define SMEM_MAIN ((OFF_RED + 32) * 4)  // ~26.7KB

// ---------------------------------------------------------------------------
// Kernel 1: one CTA (128 threads) per bt row. Rank-1 enc: enc[s,e]=1+B[s]A[e],
// with A,B exactly LINEAR in their index (derived from enc at runtime).
// ---------------------------------------------------------------------------
__global__ __launch_bounds__(128, 8) void memnet_main(
    const float* __restrict__ node_fts,   // [B,N,S]
    const float* __restrict__ edge_fts,   // [B,N,N,S]
    const float* __restrict__ graph_fts,  // [B,S]
    const float* __restrict__ adj,        // [B,N,N]
    const float* __restrict__ enc,        // [S,E]
    const float* __restrict__ qb,         // [V-1,E]
    const float* __restrict__ sb,         // [V-1,E]
    const float* __restrict__ ob,         // [V-1,E]
    const float* __restrict__ mc)         // [M=128,E]
{
    extern __shared__ float sm[];
    float*    hist  = sm + OFF_HIST;
    __half2*  gpk   = (__half2*)(sm + OFF_G);
    unsigned* sidxw = (unsigned*)(sm + OFF_SIDX);
    float*    upart = sm + OFF_UPART;
    float*    u     = sm + OFF_U;
    float*    Au    = sm + OFF_AU;
    float*    Ash   = sm + OFF_A;
    float*    Bsh   = sm + OFF_B;
    float*    probs = sm + OFF_PROBS;
    float*    red   = sm + OFF_RED;

    const int tid  = threadIdx.x;
    const int lane = tid & 31;
    const int wid  = tid >> 5;
    const int bt   = blockIdx.x;
    const int b    = bt >> 7;
    const int t    = bt & 127;
    const bool live = (t < Nc) && (tid < Nc);

    // early L2 prefetch of this CTA's edge rows + adj row
    const float* erow = edge_fts + ((size_t)((b * Nc + t) * Nc + tid)) * Sc;
    if (live)
        asm volatile("prefetch.global.L2 [%0];" :: "l"(erow));
    if (t < Nc && tid < 16)
        asm volatile("prefetch.global.L2 [%0];" ::
                     "l"(adj + (size_t)(b * Nc + t) * Nc + tid * 8));

    // ---- Phase 0: rank-1 factors; zero histograms ----
    if (tid < 16) Ash[tid] = enc[tid] - 1.f;
    if (tid < 32) Bsh[tid] = (enc[tid * 16] - 1.f) / (enc[0] - 1.f);
#pragma unroll
    for (int i = 0; i < 33; i++) hist[tid * 33 + i] = 0.f;

    // ---- Phase 1: query gather ----
    if (tid < 32) {
        float qv = (t < Nc) ? node_fts[(b * Nc + t) * Sc + tid]
                            : graph_fts[b * Sc + tid];
        int qi = (int)qv;
        qi = qi < 0 ? 0 : (qi > 127 ? 127 : qi);
        float r[16];
        if (qi < 127) {
            const float4* qr = (const float4*)(qb + qi * 16);
#pragma unroll
            for (int j = 0; j < 4; j++) {
                float4 x4 = qr[j];
                r[4*j] = x4.x; r[4*j+1] = x4.y; r[4*j+2] = x4.z; r[4*j+3] = x4.w;
            }
        } else {
#pragma unroll
            for (int e = 0; e < 16; e++) r[e] = 0.f;
        }
        float bsv = (enc[tid * 16] - 1.f) / (enc[0] - 1.f);
#pragma unroll
        for (int e = 0; e < 16; e++) {
            upart[tid * 33 + e]      = r[e];
            upart[tid * 33 + 16 + e] = bsv * r[e];
        }
    }
    __syncthreads();
    if (tid < 32) {
        float acc = 0.f;
#pragma unroll
        for (int s = 0; s < 32; s++) acc += upart[s * 33 + tid];
        red[tid] = acc;
    }
    __syncthreads();
    if (tid < 16) {
        float uu = red[tid] + Ash[tid] * red[16 + tid];
        u[tid]  = uu;
        Au[tid] = Ash[tid] * uu;
    }
    __syncthreads();

    // linear-factor registers
    const float B0 = Bsh[0], dB = Bsh[1] - Bsh[0];
    const float A0 = Ash[0], dA = Ash[1] - Ash[0];

    // ---- Phase 2: packed g table + s0; issue adj/edge loads ----
    float ureg[16], aureg[16];
    {
        const float4* uv4 = (const float4*)u;
        const float4* av4 = (const float4*)Au;
#pragma unroll
        for (int j = 0; j < 4; j++) {
            float4 x4 = uv4[j];
            ureg[4*j] = x4.x; ureg[4*j+1] = x4.y; ureg[4*j+2] = x4.z; ureg[4*j+3] = x4.w;
            float4 y4 = av4[j];
            aureg[4*j] = y4.x; aureg[4*j+1] = y4.y; aureg[4*j+2] = y4.z; aureg[4*j+3] = y4.w;
        }
    }
    // independent global loads: adj + full edge row (unconditional on adj value)
    float a = 0.f;
    float4 ev[8];
    if (live) {
        a = adj[(size_t)(b * Nc + t) * Nc + tid];
        const float4* er4 = (const float4*)erow;
#pragma unroll
        for (int j = 0; j < 8; j++) ev[j] = er4[j];
    }
    {
        float g0 = 0.f, g1 = 0.f;
        if (tid < 127) {
            const float4* sr = (const float4*)(sb + tid * 16);
#pragma unroll
            for (int j = 0; j < 4; j++) {
                float4 x4 = sr[j];
                g0 += x4.x*ureg[4*j] + x4.y*ureg[4*j+1] + x4.z*ureg[4*j+2] + x4.w*ureg[4*j+3];
                g1 += x4.x*aureg[4*j] + x4.y*aureg[4*j+1] + x4.z*aureg[4*j+2] + x4.w*aureg[4*j+3];
            }
        }
        gpk[tid] = __floats2half2_rn(g0, g1);
    }
    float s0 = 0.f;
    {
        const float4* mr = (const float4*)(mc + tid * 16);
#pragma unroll
        for (int j = 0; j < 4; j++) {
            float4 x4 = mr[j];
            s0 += x4.x*ureg[4*j] + x4.y*ureg[4*j+1] + x4.z*ureg[4*j+2] + x4.w*ureg[4*j+3];
        }
    }
    __syncthreads();

    // ---- Phase 3: clamp indices, pack, score via packed gathers ----
    int idxs[32];
    if (live && a != 0.f) {
#pragma unroll
        for (int j = 0; j < 8; j++) {
            int i0 = (int)ev[j].x, i1 = (int)ev[j].y, i2 = (int)ev[j].z, i3 = (int)ev[j].w;
            idxs[4*j]   = i0 < 0 ? 0 : (i0 > 127 ? 127 : i0);
            idxs[4*j+1] = i1 < 0 ? 0 : (i1 > 127 ? 127 : i1);
            idxs[4*j+2] = i2 < 0 ? 0 : (i2 > 127 ? 127 : i2);
            idxs[4*j+3] = i3 < 0 ? 0 : (i3 > 127 ? 127 : i3);
        }
    } else {
#pragma unroll
        for (int k = 0; k < 32; k++) idxs[k] = 0;
    }
#pragma unroll
    for (int j = 0; j < 8; j++) {
        unsigned p = (unsigned)idxs[4*j] | ((unsigned)idxs[4*j+1] << 8) |
                     ((unsigned)idxs[4*j+2] << 16) | ((unsigned)idxs[4*j+3] << 24);
        sidxw[tid * 8 + j] = p;
    }
    float score = s0;
#pragma unroll
    for (int k = 0; k < 32; k++) {
        float2 g = __half22float2(gpk[idxs[k]]);
        score += g.x + (B0 + (float)k * dB) * g.y;
    }

    // ---- Phase 4: softmax over 128 memory slots ----
    {
        float mv = score;
#pragma unroll
        for (int off = 16; off; off >>= 1)
            mv = fmaxf(mv, __shfl_xor_sync(0xFFFFFFFFu, mv, off));
        if (lane == 0) red[wid] = mv;
        __syncthreads();
        float mx = fmaxf(fmaxf(red[0], red[1]), fmaxf(red[2], red[3]));
        float ex = expf(score - mx);
        float smv = ex;
#pragma unroll
        for (int off = 16; off; off >>= 1)
            smv += __shfl_xor_sync(0xFFFFFFFFu, smv, off);
        if (lane == 0) red[4 + wid] = smv;
        __syncthreads();
        float tot = red[4] + red[5] + red[6] + red[7];
        probs[tid] = ex / tot;
    }
    __syncthreads();

    // ---- Phase 5: atomic-free scatter, one private column per s (warp 0) ----
    if (tid < 32) {
        const int sh = (tid & 3) * 8;
        const int wofs = tid >> 2;
        float* hcol = hist + tid;
        for (int m = 0; m < 128; m++) {
            float p = probs[m];
            unsigned w = sidxw[m * 8 + wofs];
            int v = (w >> sh) & 255;
            hcol[v * 33] += p;
        }
    }
    __syncthreads();

    // ---- Phase 6: c0,c1 per v=tid; contract with ob; reduce; write x ----
    {
        float c0 = 0.f, c1 = 0.f;
#pragma unroll
        for (int s = 0; s < 32; s++) {
            float h = hist[tid * 33 + s];
            c0 += h;
            c1 = fmaf(B0 + (float)s * dB, h, c1);
        }
        float part[16];
        if (tid < 127) {
            const float4* orp = (const float4*)(ob + tid * 16);
#pragma unroll
            for (int j = 0; j < 4; j++) {
                float4 x4 = orp[j];
#pragma unroll
                for (int q = 0; q < 4; q++) {
                    int e = 4*j + q;
                    float xe = (q==0)?x4.x:(q==1)?x4.y:(q==2)?x4.z:x4.w;
                    part[e] = xe * fmaf(A0 + (float)e * dA, c1, c0);
                }
            }
        } else {
#pragma unroll
            for (int e = 0; e < 16; e++) part[e] = 0.f;
        }
#pragma unroll
        for (int e = 0; e < 16; e++) {
#pragma unroll
            for (int off = 16; off; off >>= 1)
                part[e] += __shfl_xor_sync(0xFFFFFFFFu, part[e], off);
        }
        if (lane == 0) {
#pragma unroll
            for (int e = 0; e < 16; e++) upart[wid * 16 + e] = part[e];
        }
    }
    __syncthreads();
    if (tid < 16) {
        float o = upart[tid] + upart[16 + tid] + upart[32 + tid] + upart[48 + tid];
        g_xbuf[bt * 16 + tid] = u[tid] + o;
    }
}

// ---------------------------------------------------------------------------
// Kernel 2 (fused): ret = relu(x @ W_out) @ W_fin; out = ret[t] + ret[127].
// grid = 16 b * 8 chunks; each CTA recomputes ret[127] (cheap) and writes out.
// ---------------------------------------------------------------------------
#define SMEM_OUT ((2048 + 16384 + 64 + 512 + 128) * 4)
__global__ __launch_bounds__(128) void memnet_out(
    const float* __restrict__ W_out,   // [16,128]
    const float* __restrict__ W_fin,   // [128,128]
    float* __restrict__ out)           // [16,127,128]
{
    extern __shared__ float sm[];
    float* Wo  = sm;            // 2048
    float* Wf  = Wo + 2048;     // 16384
    float* xs  = Wf + 16384;    // 64
    float* hsT = xs + 64;       // [128][4]
    float* h1  = hsT + 512;     // 128

    const int tid = threadIdx.x;
    const int b   = blockIdx.x >> 3;
    const int cg  = blockIdx.x & 7;

    for (int i = tid; i < 2048; i += 128)  Wo[i] = W_out[i];
    for (int i = tid; i < 16384; i += 128) Wf[i] = W_fin[i];
    if (tid < 16) xs[tid] = g_xbuf[(b * 128 + 127) * 16 + tid];
    __syncthreads();

    // ret127
    float hh = 0.f;
#pragma unroll
    for (int e = 0; e < 16; e++) hh += xs[e] * Wo[e * 128 + tid];
    h1[tid] = fmaxf(hh, 0.f);
    __syncthreads();
    float r127 = 0.f;
#pragma unroll 8
    for (int l = 0; l < 128; l++) r127 = fmaf(h1[l], Wf[l * 128 + tid], r127);

    // 4 quads of 4 t each
#pragma unroll 1
    for (int q = 0; q < 4; q++) {
        const int t0 = cg * 16 + q * 4;
        __syncthreads();
        if (tid < 64) xs[tid] = g_xbuf[(b * 128 + t0) * 16 + tid];
        __syncthreads();
#pragma unroll
        for (int qq = 0; qq < 4; qq++) {
            float aa = 0.f;
#pragma unroll
            for (int e = 0; e < 16; e++)
                aa += xs[qq * 16 + e] * Wo[e * 128 + tid];
            hsT[tid * 4 + qq] = fmaxf(aa, 0.f);
        }
        __syncthreads();
        float a0 = 0.f, a1 = 0.f, a2 = 0.f, a3 = 0.f;
#pragma unroll 8
        for (int l = 0; l < 128; l++) {
            float wv = Wf[l * 128 + tid];
            float4 hv = ((const float4*)hsT)[l];
            a0 = fmaf(hv.x, wv, a0);
            a1 = fmaf(hv.y, wv, a1);
            a2 = fmaf(hv.z, wv, a2);
            a3 = fmaf(hv.w, wv, a3);
        }
        float av[4] = {a0, a1, a2, a3};
#pragma unroll
        for (int qq = 0; qq < 4; qq++) {
            int t = t0 + qq;
            if (t < 127)
                out[((b * Nc) + t) * 128 + tid] = av[qq] + r127;
        }
    }
}

extern "C" void kernel_launch(void* const* d_in, const int* in_sizes, int n_in,
                              void* d_out, int out_size)
{
    const float* node_fts  = (const float*)d_in[0];
    const float* edge_fts  = (const float*)d_in[1];
    const float* graph_fts = (const float*)d_in[2];
    const float* adj       = (const float*)d_in[3];
    // d_in[4] hidden: unused
    const float* enc       = (const float*)d_in[5];
    const float* qb        = (const float*)d_in[6];
    const float* sb        = (const float*)d_in[7];
    const float* ob        = (const float*)d_in[8];
    const float* mc        = (const float*)d_in[9];
    // d_in[10] W_int: unused (num_hops == 1)
    const float* W_out     = (const float*)d_in[11];
    const float* W_fin     = (const float*)d_in[12];
    float* out = (float*)d_out;

    cudaFuncSetAttribute(memnet_main, cudaFuncAttributeMaxDynamicSharedMemorySize, SMEM_MAIN);
    cudaFuncSetAttribute(memnet_out, cudaFuncAttributeMaxDynamicSharedMemorySize, SMEM_OUT);

    memnet_main<<<BTc, 128, SMEM_MAIN>>>(node_fts, edge_fts, graph_fts, adj, enc,
                                         qb, sb, ob, mc);
    memnet_out<<<128, 128, SMEM_OUT>>>(W_out, W_fin, out);
}

// round 15
// speedup vs baseline: 1.1153x; 1.1153x over previous
#include <cuda_runtime.h>
#include <cuda_fp16.h>
#include <math.h>

#define Bc 16
#define Nc 127
#define Sc 32
#define Ec 16
#define Vc 128
#define BTc 2048

__device__ float g_xbuf[BTc * Ec];     // u + o per bt

// smem layout (floats)
#define OFF_HIST  0                     // [128][33] per-s private histograms
#define OFF_G     (128*33)              // __half2[128] packed (g0,g1)
#define OFF_SIDX  (OFF_G + 128)         // uint32 [128][8]
#define OFF_UPART (OFF_SIDX + 1024)     // [32][33]
#define OFF_U     (OFF_UPART + 1056)    // [16]
#define OFF_AU    (OFF_U + 16)          // [16]
#define OFF_A     (OFF_AU + 16)         // [16]
#define OFF_B     (OFF_A + 16)          // [32]
#define OFF_PROBS (OFF_B + 32)          // [128]
#define OFF_RED   (OFF_PROBS + 128)     // [32]
#define SMEM_MAIN ((OFF_RED + 32) * 4)  // ~26.7KB

// ---------------------------------------------------------------------------
// Kernel 1: one CTA (128 threads) per bt row. Rank-1 enc: enc[s,e]=1+B[s]A[e],
// with A,B exactly LINEAR in their index (derived from enc at runtime).
// (UNCHANGED from the R4-measured version — isolating the tail fix.)
// ---------------------------------------------------------------------------
__global__ __launch_bounds__(128, 8) void memnet_main(
    const float* __restrict__ node_fts,   // [B,N,S]
    const float* __restrict__ edge_fts,   // [B,N,N,S]
    const float* __restrict__ graph_fts,  // [B,S]
    const float* __restrict__ adj,        // [B,N,N]
    const float* __restrict__ enc,        // [S,E]
    const float* __restrict__ qb,         // [V-1,E]
    const float* __restrict__ sb,         // [V-1,E]
    const float* __restrict__ ob,         // [V-1,E]
    const float* __restrict__ mc)         // [M=128,E]
{
    extern __shared__ float sm[];
    float*    hist  = sm + OFF_HIST;
    __half2*  gpk   = (__half2*)(sm + OFF_G);
    unsigned* sidxw = (unsigned*)(sm + OFF_SIDX);
    float*    upart = sm + OFF_UPART;
    float*    u     = sm + OFF_U;
    float*    Au    = sm + OFF_AU;
    float*    Ash   = sm + OFF_A;
    float*    Bsh   = sm + OFF_B;
    float*    probs = sm + OFF_PROBS;
    float*    red   = sm + OFF_RED;

    const int tid  = threadIdx.x;
    const int lane = tid & 31;
    const int wid  = tid >> 5;
    const int bt   = blockIdx.x;
    const int b    = bt >> 7;
    const int t    = bt & 127;
    const bool live = (t < Nc) && (tid < Nc);

    // early L2 prefetch of this CTA's edge rows + adj row
    const float* erow = edge_fts + ((size_t)((b * Nc + t) * Nc + tid)) * Sc;
    if (live)
        asm volatile("prefetch.global.L2 [%0];" :: "l"(erow));
    if (t < Nc && tid < 16)
        asm volatile("prefetch.global.L2 [%0];" ::
                     "l"(adj + (size_t)(b * Nc + t) * Nc + tid * 8));

    // ---- Phase 0: rank-1 factors; zero histograms ----
    if (tid < 16) Ash[tid] = enc[tid] - 1.f;
    if (tid < 32) Bsh[tid] = (enc[tid * 16] - 1.f) / (enc[0] - 1.f);
#pragma unroll
    for (int i = 0; i < 33; i++) hist[tid * 33 + i] = 0.f;

    // ---- Phase 1: query gather ----
    if (tid < 32) {
        float qv = (t < Nc) ? node_fts[(b * Nc + t) * Sc + tid]
                            : graph_fts[b * Sc + tid];
        int qi = (int)qv;
        qi = qi < 0 ? 0 : (qi > 127 ? 127 : qi);
        float r[16];
        if (qi < 127) {
            const float4* qr = (const float4*)(qb + qi * 16);
#pragma unroll
            for (int j = 0; j < 4; j++) {
                float4 x4 = qr[j];
                r[4*j] = x4.x; r[4*j+1] = x4.y; r[4*j+2] = x4.z; r[4*j+3] = x4.w;
            }
        } else {
#pragma unroll
            for (int e = 0; e < 16; e++) r[e] = 0.f;
        }
        float bsv = (enc[tid * 16] - 1.f) / (enc[0] - 1.f);
#pragma unroll
        for (int e = 0; e < 16; e++) {
            upart[tid * 33 + e]      = r[e];
            upart[tid * 33 + 16 + e] = bsv * r[e];
        }
    }
    __syncthreads();
    if (tid < 32) {
        float acc = 0.f;
#pragma unroll
        for (int s = 0; s < 32; s++) acc += upart[s * 33 + tid];
        red[tid] = acc;
    }
    __syncthreads();
    if (tid < 16) {
        float uu = red[tid] + Ash[tid] * red[16 + tid];
        u[tid]  = uu;
        Au[tid] = Ash[tid] * uu;
    }
    __syncthreads();

    // linear-factor registers
    const float B0 = Bsh[0], dB = Bsh[1] - Bsh[0];
    const float A0 = Ash[0], dA = Ash[1] - Ash[0];

    // ---- Phase 2: packed g table + s0; issue adj/edge loads ----
    float ureg[16], aureg[16];
    {
        const float4* uv4 = (const float4*)u;
        const float4* av4 = (const float4*)Au;
#pragma unroll
        for (int j = 0; j < 4; j++) {
            float4 x4 = uv4[j];
            ureg[4*j] = x4.x; ureg[4*j+1] = x4.y; ureg[4*j+2] = x4.z; ureg[4*j+3] = x4.w;
            float4 y4 = av4[j];
            aureg[4*j] = y4.x; aureg[4*j+1] = y4.y; aureg[4*j+2] = y4.z; aureg[4*j+3] = y4.w;
        }
    }
    // independent global loads: adj + full edge row (unconditional on adj value)
    float a = 0.f;
    float4 ev[8];
    if (live) {
        a = adj[(size_t)(b * Nc + t) * Nc + tid];
        const float4* er4 = (const float4*)erow;
#pragma unroll
        for (int j = 0; j < 8; j++) ev[j] = er4[j];
    }
    {
        float g0 = 0.f, g1 = 0.f;
        if (tid < 127) {
            const float4* sr = (const float4*)(sb + tid * 16);
#pragma unroll
            for (int j = 0; j < 4; j++) {
                float4 x4 = sr[j];
                g0 += x4.x*ureg[4*j] + x4.y*ureg[4*j+1] + x4.z*ureg[4*j+2] + x4.w*ureg[4*j+3];
                g1 += x4.x*aureg[4*j] + x4.y*aureg[4*j+1] + x4.z*aureg[4*j+2] + x4.w*aureg[4*j+3];
            }
        }
        gpk[tid] = __floats2half2_rn(g0, g1);
    }
    float s0 = 0.f;
    {
        const float4* mr = (const float4*)(mc + tid * 16);
#pragma unroll
        for (int j = 0; j < 4; j++) {
            float4 x4 = mr[j];
            s0 += x4.x*ureg[4*j] + x4.y*ureg[4*j+1] + x4.z*ureg[4*j+2] + x4.w*ureg[4*j+3];
        }
    }
    __syncthreads();

    // ---- Phase 3: clamp indices, pack, score via packed gathers ----
    int idxs[32];
    if (live && a != 0.f) {
#pragma unroll
        for (int j = 0; j < 8; j++) {
            int i0 = (int)ev[j].x, i1 = (int)ev[j].y, i2 = (int)ev[j].z, i3 = (int)ev[j].w;
            idxs[4*j]   = i0 < 0 ? 0 : (i0 > 127 ? 127 : i0);
            idxs[4*j+1] = i1 < 0 ? 0 : (i1 > 127 ? 127 : i1);
            idxs[4*j+2] = i2 < 0 ? 0 : (i2 > 127 ? 127 : i2);
            idxs[4*j+3] = i3 < 0 ? 0 : (i3 > 127 ? 127 : i3);
        }
    } else {
#pragma unroll
        for (int k = 0; k < 32; k++) idxs[k] = 0;
    }
#pragma unroll
    for (int j = 0; j < 8; j++) {
        unsigned p = (unsigned)idxs[4*j] | ((unsigned)idxs[4*j+1] << 8) |
                     ((unsigned)idxs[4*j+2] << 16) | ((unsigned)idxs[4*j+3] << 24);
        sidxw[tid * 8 + j] = p;
    }
    float score = s0;
#pragma unroll
    for (int k = 0; k < 32; k++) {
        float2 g = __half22float2(gpk[idxs[k]]);
        score += g.x + (B0 + (float)k * dB) * g.y;
    }

    // ---- Phase 4: softmax over 128 memory slots ----
    {
        float mv = score;
#pragma unroll
        for (int off = 16; off; off >>= 1)
            mv = fmaxf(mv, __shfl_xor_sync(0xFFFFFFFFu, mv, off));
        if (lane == 0) red[wid] = mv;
        __syncthreads();
        float mx = fmaxf(fmaxf(red[0], red[1]), fmaxf(red[2], red[3]));
        float ex = expf(score - mx);
        float smv = ex;
#pragma unroll
        for (int off = 16; off; off >>= 1)
            smv += __shfl_xor_sync(0xFFFFFFFFu, smv, off);
        if (lane == 0) red[4 + wid] = smv;
        __syncthreads();
        float tot = red[4] + red[5] + red[6] + red[7];
        probs[tid] = ex / tot;
    }
    __syncthreads();

    // ---- Phase 5: atomic-free scatter, one private column per s (warp 0) ----
    if (tid < 32) {
        const int sh = (tid & 3) * 8;
        const int wofs = tid >> 2;
        float* hcol = hist + tid;
        for (int m = 0; m < 128; m++) {
            float p = probs[m];
            unsigned w = sidxw[m * 8 + wofs];
            int v = (w >> sh) & 255;
            hcol[v * 33] += p;
        }
    }
    __syncthreads();

    // ---- Phase 6: c0,c1 per v=tid; contract with ob; reduce; write x ----
    {
        float c0 = 0.f, c1 = 0.f;
#pragma unroll
        for (int s = 0; s < 32; s++) {
            float h = hist[tid * 33 + s];
            c0 += h;
            c1 = fmaf(B0 + (float)s * dB, h, c1);
        }
        float part[16];
        if (tid < 127) {
            const float4* orp = (const float4*)(ob + tid * 16);
#pragma unroll
            for (int j = 0; j < 4; j++) {
                float4 x4 = orp[j];
#pragma unroll
                for (int q = 0; q < 4; q++) {
                    int e = 4*j + q;
                    float xe = (q==0)?x4.x:(q==1)?x4.y:(q==2)?x4.z:x4.w;
                    part[e] = xe * fmaf(A0 + (float)e * dA, c1, c0);
                }
            }
        } else {
#pragma unroll
            for (int e = 0; e < 16; e++) part[e] = 0.f;
        }
#pragma unroll
        for (int e = 0; e < 16; e++) {
#pragma unroll
            for (int off = 16; off; off >>= 1)
                part[e] += __shfl_xor_sync(0xFFFFFFFFu, part[e], off);
        }
        if (lane == 0) {
#pragma unroll
            for (int e = 0; e < 16; e++) upart[wid * 16 + e] = part[e];
        }
    }
    __syncthreads();
    if (tid < 16) {
        float o = upart[tid] + upart[16 + tid] + upart[32 + tid] + upart[48 + tid];
        g_xbuf[bt * 16 + tid] = u[tid] + o;
    }
}

// ---------------------------------------------------------------------------
// Kernel 2 (tail): out[b,t,:] = ret[b,t,:] + ret[b,127,:] where
//   ret = relu(x @ W_out) @ W_fin.
// grid = 512 (16 b x 32 chunks of 4 t). W_fin read from GLOBAL (L1-resident);
// smem ~11KB so many CTAs/SM. 5 accumulators/thread (4 rows + r127).
// ---------------------------------------------------------------------------
#define SMEM_OUT ((2048 + 64 + 16 + 512 + 128) * 4)
__global__ __launch_bounds__(128) void memnet_out(
    const float* __restrict__ W_out,   // [16,128]
    const float* __restrict__ W_fin,   // [128,128]
    float* __restrict__ out)           // [16,127,128]
{
    extern __shared__ float sm[];
    float* Wo  = sm;            // 2048
    float* xs  = Wo + 2048;     // 64  (4 t-rows of x)
    float* x7  = xs + 64;       // 16  (row t=127)
    float* hsT = x7 + 16;       // [128][4]
    float* h1  = hsT + 512;     // 128

    const int tid = threadIdx.x;
    const int b   = blockIdx.x >> 5;
    const int t0  = (blockIdx.x & 31) * 4;

    for (int i = tid; i < 2048; i += 128) Wo[i] = W_out[i];
    if (tid < 64)       xs[tid]      = g_xbuf[(b * 128 + t0) * 16 + tid];
    else if (tid < 80)  x7[tid - 64] = g_xbuf[(b * 128 + 127) * 16 + (tid - 64)];
    __syncthreads();

    // hidden layer: 4 rows + row127, relu
#pragma unroll
    for (int qq = 0; qq < 4; qq++) {
        float aa = 0.f;
#pragma unroll
        for (int e = 0; e < 16; e++)
            aa += xs[qq * 16 + e] * Wo[e * 128 + tid];
        hsT[tid * 4 + qq] = fmaxf(aa, 0.f);
    }
    {
        float aa = 0.f;
#pragma unroll
        for (int e = 0; e < 16; e++)
            aa += x7[e] * Wo[e * 128 + tid];
        h1[tid] = fmaxf(aa, 0.f);
    }
    __syncthreads();

    // final layer: W_fin streamed from global (coalesced, L1-hot)
    float a0 = 0.f, a1 = 0.f, a2 = 0.f, a3 = 0.f, a7 = 0.f;
#pragma unroll 8
    for (int l = 0; l < 128; l++) {
        float wv = __ldg(W_fin + l * 128 + tid);
        float4 hv = ((const float4*)hsT)[l];
        float h7 = h1[l];
        a0 = fmaf(hv.x, wv, a0);
        a1 = fmaf(hv.y, wv, a1);
        a2 = fmaf(hv.z, wv, a2);
        a3 = fmaf(hv.w, wv, a3);
        a7 = fmaf(h7,  wv, a7);
    }
    float av[4] = {a0, a1, a2, a3};
#pragma unroll
    for (int qq = 0; qq < 4; qq++) {
        int t = t0 + qq;
        if (t < 127)
            out[(b * Nc + t) * 128 + tid] = av[qq] + a7;
    }
}

extern "C" void kernel_launch(void* const* d_in, const int* in_sizes, int n_in,
                              void* d_out, int out_size)
{
    const float* node_fts  = (const float*)d_in[0];
    const float* edge_fts  = (const float*)d_in[1];
    const float* graph_fts = (const float*)d_in[2];
    const float* adj       = (const float*)d_in[3];
    // d_in[4] hidden: unused
    const float* enc       = (const float*)d_in[5];
    const float* qb        = (const float*)d_in[6];
    const float* sb        = (const float*)d_in[7];
    const float* ob        = (const float*)d_in[8];
    const float* mc        = (const float*)d_in[9];
    // d_in[10] W_int: unused (num_hops == 1)
    const float* W_out     = (const float*)d_in[11];
    const float* W_fin     = (const float*)d_in[12];
    float* out = (float*)d_out;

    cudaFuncSetAttribute(memnet_main, cudaFuncAttributeMaxDynamicSharedMemorySize, SMEM_MAIN);

    memnet_main<<<BTc, 128, SMEM_MAIN>>>(node_fts, edge_fts, graph_fts, adj, enc,
                                         qb, sb, ob, mc);
    memnet_out<<<512, 128, SMEM_OUT>>>(W_out, W_fin, out);
}